// round 15
// baseline (speedup 1.0000x reference)
#include <cuda_runtime.h>
#include <cuda_fp16.h>
#include <math.h>
#include <stdint.h>

#define BB   4
#define CC   2048
#define DD   512
#define NHH  8
#define MTOT (BB * CC)      // 8192
#define HD   (NHH * DD)     // 4096

// ---------------- scratch (device globals: no allocation allowed) ----------------
__device__ __half g_Xh [(size_t)MTOT * DD];
__device__ __half g_Qh [(size_t)NHH * MTOT * DD];     // [hb][c][d]
__device__ __half g_Kh [(size_t)NHH * MTOT * DD];
__device__ __half g_Vh [(size_t)NHH * MTOT * DD];     // [hb][c][d]
__device__ __half g_VTh[(size_t)NHH * BB * DD * CC];  // [hb][d][c]
__device__ __half g_Oh [(size_t)MTOT * HD];           // [b*C+c][h*D+d]
__device__ __half g_WqTh[(size_t)NHH * DD * DD];      // [h][n][k]
__device__ __half g_WkTh[(size_t)NHH * DD * DD];
__device__ __half g_WvTh[(size_t)NHH * DD * DD];
__device__ __half g_WoTh[(size_t)DD * HD];            // [n][k]
__device__ float  g_ctab[CC * (DD / 2)];
__device__ float  g_stab[CC * (DD / 2)];

// ---------------- RoPE cos/sin table ----------------
__global__ void rope_table_kernel() {
    int idx = blockIdx.x * blockDim.x + threadIdx.x;
    if (idx >= CC * (DD / 2)) return;
    int c = idx / (DD / 2);
    int i = idx - c * (DD / 2);
    double theta = exp((-2.0 * (double)i / (double)DD) * log(10000.0));
    double ang = fmod((double)c * theta, 6.283185307179586476925287);
    float af = (float)ang;
    g_ctab[idx] = cosf(af);
    g_stab[idx] = sinf(af);
}

// ---------------- x -> half ----------------
__global__ void conv_x_kernel(const float* __restrict__ x) {
    int i = blockIdx.x * blockDim.x + threadIdx.x;
    if (i < MTOT * DD) g_Xh[i] = __float2half_rn(x[i]);
}

// ---------------- fp32 [R][C] -> half [C][R] (batched over z) ----------------
__global__ void transpose_h_kernel(const float* __restrict__ src, __half* __restrict__ dst,
                                   int R, int C) {
    __shared__ float tsm[32][33];
    src += (size_t)blockIdx.z * R * C;
    dst += (size_t)blockIdx.z * R * C;
    int r0 = blockIdx.y * 32, c0 = blockIdx.x * 32;
    int x = threadIdx.x, y = threadIdx.y;
#pragma unroll
    for (int i = 0; i < 32; i += 8)
        tsm[y + i][x] = src[(size_t)(r0 + y + i) * C + c0 + x];
    __syncthreads();
#pragma unroll
    for (int i = 0; i < 32; i += 8)
        dst[(size_t)(c0 + y + i) * R + r0 + x] = __float2half_rn(tsm[x][y + i]);
}

// ---------------- V [hb][c][d] -> VT [hb][d][c] (half) ----------------
__global__ void vtrans_kernel() {
    __shared__ __half t[32][33];
    const int hb = blockIdx.z;
    const int c0 = blockIdx.x * 32, d0 = blockIdx.y * 32;
    const __half* src = g_Vh + ((size_t)hb * CC + c0) * DD + d0;
    __half* dst = g_VTh + (size_t)hb * DD * CC;
    int x = threadIdx.x, y = threadIdx.y;
#pragma unroll
    for (int i = 0; i < 32; i += 8)
        t[y + i][x] = src[(size_t)(y + i) * DD + x];
    __syncthreads();
#pragma unroll
    for (int i = 0; i < 32; i += 8)
        dst[(size_t)(d0 + y + i) * CC + c0 + x] = t[x][y + i];
}

// ---------------- fp16 MMA ----------------
__device__ __forceinline__ void mma16(float* d, const uint32_t* a, const uint32_t* b) {
    asm volatile(
        "mma.sync.aligned.m16n8k16.row.col.f32.f16.f16.f32 "
        "{%0,%1,%2,%3}, {%4,%5,%6,%7}, {%8,%9}, {%0,%1,%2,%3};"
        : "+f"(d[0]), "+f"(d[1]), "+f"(d[2]), "+f"(d[3])
        : "r"(a[0]), "r"(a[1]), "r"(a[2]), "r"(a[3]),
          "r"(b[0]), "r"(b[1]));
}

// ================= generic fp16 GEMM (unchanged from R14) =================
#define AHW    40
#define ASZ_H  (2 * 128 * AHW)
#define BSZ_H  (2 * 256 * AHW)
#define SMEM_H (size_t)((ASZ_H + BSZ_H) * 2)

__device__ __forceinline__ void gemm_bt_h(
    const __half* __restrict__ Ag, int lda,
    const __half* __restrict__ Bg, int ldb,
    int nchunks, float (&acc)[4][8][4])
{
    extern __shared__ __half smh[];
    __half (*As)[128][AHW] = (__half(*)[128][AHW])smh;
    __half (*Bs)[256][AHW] = (__half(*)[256][AHW])(smh + ASZ_H);

    const int tid  = threadIdx.x;
    const int lane = tid & 31, wid = tid >> 5;
    const int g = lane >> 2, t4 = lane & 3;
    const int wm = (wid >> 2) * 64, wn = (wid & 3) * 64;

    uint4 av[2], bv[4];
#pragma unroll
    for (int i = 0; i < 2; ++i) {
        int s = tid + i * 256;
        av[i] = *(const uint4*)(Ag + (size_t)(s >> 2) * lda + (s & 3) * 8);
    }
#pragma unroll
    for (int i = 0; i < 4; ++i) {
        int s = tid + i * 256;
        bv[i] = *(const uint4*)(Bg + (size_t)(s >> 2) * ldb + (s & 3) * 8);
    }

    for (int kt = 0; kt < nchunks; ++kt) {
        const int buf = kt & 1;
#pragma unroll
        for (int i = 0; i < 2; ++i) {
            int s = tid + i * 256;
            *(uint4*)&As[buf][s >> 2][(s & 3) * 8] = av[i];
        }
#pragma unroll
        for (int i = 0; i < 4; ++i) {
            int s = tid + i * 256;
            *(uint4*)&Bs[buf][s >> 2][(s & 3) * 8] = bv[i];
        }
        __syncthreads();
        if (kt + 1 < nchunks) {
            const __half* Ap = Ag + (kt + 1) * 32;
            const __half* Bp = Bg + (kt + 1) * 32;
#pragma unroll
            for (int i = 0; i < 2; ++i) {
                int s = tid + i * 256;
                av[i] = *(const uint4*)(Ap + (size_t)(s >> 2) * lda + (s & 3) * 8);
            }
#pragma unroll
            for (int i = 0; i < 4; ++i) {
                int s = tid + i * 256;
                bv[i] = *(const uint4*)(Bp + (size_t)(s >> 2) * ldb + (s & 3) * 8);
            }
        }
#pragma unroll
        for (int k0 = 0; k0 < 32; k0 += 16) {
            uint32_t a[4][4], b[8][2];
#pragma unroll
            for (int mi = 0; mi < 4; ++mi) {
                const int r = wm + mi * 16 + g;
                a[mi][0] = *(const uint32_t*)&As[buf][r][k0 + 2 * t4];
                a[mi][1] = *(const uint32_t*)&As[buf][r + 8][k0 + 2 * t4];
                a[mi][2] = *(const uint32_t*)&As[buf][r][k0 + 2 * t4 + 8];
                a[mi][3] = *(const uint32_t*)&As[buf][r + 8][k0 + 2 * t4 + 8];
            }
#pragma unroll
            for (int ni = 0; ni < 8; ++ni) {
                const int cn = wn + ni * 8 + g;
                b[ni][0] = *(const uint32_t*)&Bs[buf][cn][k0 + 2 * t4];
                b[ni][1] = *(const uint32_t*)&Bs[buf][cn][k0 + 2 * t4 + 8];
            }
#pragma unroll
            for (int mi = 0; mi < 4; ++mi)
#pragma unroll
                for (int ni = 0; ni < 8; ++ni)
                    mma16(acc[mi][ni], a[mi], b[ni]);
        }
    }
}

#define ACC_INIT(acc)                                   \
    float acc[4][8][4];                                 \
    _Pragma("unroll")                                   \
    for (int _i = 0; _i < 4; ++_i)                      \
        _Pragma("unroll")                               \
        for (int _j = 0; _j < 8; ++_j)                  \
            _Pragma("unroll")                           \
            for (int _r = 0; _r < 4; ++_r) acc[_i][_j][_r] = 0.f;

// ---------------- Kernel 1: QKV projection + bias + RoPE ----------------
__global__ __launch_bounds__(256, 1)
void qkv_f16(const float* __restrict__ bq, const float* __restrict__ bk,
             const float* __restrict__ bvv) {
    const int z = blockIdx.z;
    const int h = z / 3, t = z - 3 * h;
    const __half* WT = (t == 0 ? g_WqTh : (t == 1 ? g_WkTh : g_WvTh)) + (size_t)h * DD * DD;
    const float* bias = (t == 0 ? bq : (t == 1 ? bk : bvv)) + h * DD;
    __half* Out = (t == 0 ? g_Qh : (t == 1 ? g_Kh : g_Vh)) + (size_t)h * MTOT * DD;

    const int m0 = blockIdx.y * 128, n0 = blockIdx.x * 256;
    ACC_INIT(acc);
    gemm_bt_h(g_Xh + (size_t)m0 * DD, DD, WT + (size_t)n0 * DD, DD, DD / 32, acc);

    const int lane = threadIdx.x & 31, wid = threadIdx.x >> 5;
    const int g = lane >> 2, t4 = lane & 3;
    const int wm = (wid >> 2) * 64, wn = (wid & 3) * 64;

#pragma unroll
    for (int mi = 0; mi < 4; ++mi) {
        const int mlo = m0 + wm + mi * 16 + g;
        const int mhi = mlo + 8;
#pragma unroll
        for (int ni = 0; ni < 8; ++ni) {
            const int n = n0 + wn + ni * 8 + 2 * t4;
            float2 bb = *(const float2*)(bias + n);
            float o0 = acc[mi][ni][0] + bb.x;
            float o1 = acc[mi][ni][1] + bb.y;
            float o2 = acc[mi][ni][2] + bb.x;
            float o3 = acc[mi][ni][3] + bb.y;
            if (t < 2) {
                const int p = n >> 1;
                const int clo = mlo & (CC - 1), chi = mhi & (CC - 1);
                float cs = g_ctab[clo * 256 + p], sn = g_stab[clo * 256 + p];
                float e = o0, od = o1;
                o0 = e * cs - od * sn; o1 = e * sn + od * cs;
                cs = g_ctab[chi * 256 + p]; sn = g_stab[chi * 256 + p];
                e = o2; od = o3;
                o2 = e * cs - od * sn; o3 = e * sn + od * cs;
            }
            *(__half2*)(Out + (size_t)mlo * DD + n) = __floats2half2_rn(o0, o1);
            *(__half2*)(Out + (size_t)mhi * DD + n) = __floats2half2_rn(o2, o3);
        }
    }
}

// ================= fused flash attention =================
// CTA: 256 threads (8 warps = 2(q) x 4), q-block 64, k-block 128.
// SMEM halfs layout:
#define FQ_OFF   0
#define FQ_LD    528
#define FK_OFF   (64 * FQ_LD)                 // 33792
#define FK_LD    72
#define FK_BUF   (128 * FK_LD)                // 9216
#define FP_OFF   (FK_OFF + 2 * FK_BUF)        // 52224
#define FP_LD    136
#define FV_OFF   (FP_OFF + 64 * FP_LD)        // 60928
#define FV_LD    40
#define FV_BUF   (512 * FV_LD)                // 20480
#define F_HALFS  (FV_OFF + 2 * FV_BUF)        // 101888
#define SMEM_FLASH ((size_t)F_HALFS * 2 + 448 * 4)   // 205568 B

__global__ __launch_bounds__(256, 1)
void flash_f16() {
    extern __shared__ __half smf[];
    float* sm_m     = (float*)(smf + F_HALFS);
    float* sm_l     = sm_m + 64;
    float* sm_scale = sm_l + 64;
    float* sm_red   = sm_scale + 64;   // [4][64]

    const int tid = threadIdx.x, lane = tid & 31, wid = tid >> 5;
    const int g = lane >> 2, t4 = lane & 3;
    const int wm  = (wid >> 2) * 32;
    const int wn  = (wid & 3) * 32;
    const int wnd = (wid & 3) * 128;
    const int hb  = blockIdx.y;
    const int qb  = 31 - (int)blockIdx.x;     // heavy blocks first
    const int h = hb >> 2, b = hb & 3;
    const int q0 = qb * 64;
    const int nkb = (qb + 2) >> 1;

    // load Q tile (64 x 512)
    {
        const __half* Qg = g_Qh + ((size_t)hb * CC + q0) * DD;
#pragma unroll
        for (int i = 0; i < 16; ++i) {
            int s = tid + i * 256;
            int row = s >> 6, col = (s & 63) * 8;
            *(uint4*)(smf + FQ_OFF + row * FQ_LD + col) =
                *(const uint4*)(Qg + (size_t)row * DD + col);
        }
    }
    if (tid < 64) { sm_m[tid] = -1e30f; sm_l[tid] = 0.f; }

    float acc_o[2][16][4];
#pragma unroll
    for (int mi = 0; mi < 2; ++mi)
#pragma unroll
        for (int ni = 0; ni < 16; ++ni)
#pragma unroll
            for (int r = 0; r < 4; ++r) acc_o[mi][ni][r] = 0.f;

    __syncthreads();
    const float scl = 0.04419417382415922f;   // 1/sqrt(512)

    for (int kb = 0; kb < nkb; ++kb) {
        // ---------- Phase A: S = Q K^T ----------
        const __half* Kg = g_Kh + ((size_t)hb * CC + kb * 128) * DD;
        float acc_s[2][4][4];
#pragma unroll
        for (int mi = 0; mi < 2; ++mi)
#pragma unroll
            for (int ni = 0; ni < 4; ++ni)
#pragma unroll
                for (int r = 0; r < 4; ++r) acc_s[mi][ni][r] = 0.f;

        uint4 kreg[4];
#pragma unroll
        for (int i = 0; i < 4; ++i) {
            int s = tid + i * 256;
            kreg[i] = *(const uint4*)(Kg + (size_t)(s >> 3) * DD + (s & 7) * 8);
        }
        for (int dc = 0; dc < 8; ++dc) {
            __half* Kb = smf + FK_OFF + (dc & 1) * FK_BUF;
#pragma unroll
            for (int i = 0; i < 4; ++i) {
                int s = tid + i * 256;
                *(uint4*)(Kb + (s >> 3) * FK_LD + (s & 7) * 8) = kreg[i];
            }
            __syncthreads();
            if (dc < 7) {
#pragma unroll
                for (int i = 0; i < 4; ++i) {
                    int s = tid + i * 256;
                    kreg[i] = *(const uint4*)(Kg + (size_t)(s >> 3) * DD +
                                              (dc + 1) * 64 + (s & 7) * 8);
                }
            }
#pragma unroll
            for (int k0 = 0; k0 < 64; k0 += 16) {
                uint32_t a[2][4], bf[4][2];
#pragma unroll
                for (int mi = 0; mi < 2; ++mi) {
                    const __half* ap = smf + FQ_OFF + (wm + mi * 16 + g) * FQ_LD +
                                       dc * 64 + k0 + 2 * t4;
                    a[mi][0] = *(const uint32_t*)ap;
                    a[mi][1] = *(const uint32_t*)(ap + 8 * FQ_LD);
                    a[mi][2] = *(const uint32_t*)(ap + 8);
                    a[mi][3] = *(const uint32_t*)(ap + 8 * FQ_LD + 8);
                }
#pragma unroll
                for (int ni = 0; ni < 4; ++ni) {
                    const __half* bp = Kb + (wn + ni * 8 + g) * FK_LD + k0 + 2 * t4;
                    bf[ni][0] = *(const uint32_t*)bp;
                    bf[ni][1] = *(const uint32_t*)(bp + 8);
                }
#pragma unroll
                for (int mi = 0; mi < 2; ++mi)
#pragma unroll
                    for (int ni = 0; ni < 4; ++ni)
                        mma16(acc_s[mi][ni], a[mi], bf[ni]);
            }
        }

        // ---------- Phase B: online softmax ----------
        float mr[2][2] = {{-1e30f, -1e30f}, {-1e30f, -1e30f}};
#pragma unroll
        for (int mi = 0; mi < 2; ++mi) {
            const int q_lo = q0 + wm + mi * 16 + g;
            const int q_hi = q_lo + 8;
#pragma unroll
            for (int ni = 0; ni < 4; ++ni) {
                const int kcol = kb * 128 + wn + ni * 8 + 2 * t4;
                float v0 = (kcol     <= q_lo) ? acc_s[mi][ni][0] * scl : -1e30f;
                float v1 = (kcol + 1 <= q_lo) ? acc_s[mi][ni][1] * scl : -1e30f;
                float v2 = (kcol     <= q_hi) ? acc_s[mi][ni][2] * scl : -1e30f;
                float v3 = (kcol + 1 <= q_hi) ? acc_s[mi][ni][3] * scl : -1e30f;
                acc_s[mi][ni][0] = v0; acc_s[mi][ni][1] = v1;
                acc_s[mi][ni][2] = v2; acc_s[mi][ni][3] = v3;
                mr[mi][0] = fmaxf(mr[mi][0], fmaxf(v0, v1));
                mr[mi][1] = fmaxf(mr[mi][1], fmaxf(v2, v3));
            }
        }
#pragma unroll
        for (int off = 1; off <= 2; off <<= 1)
#pragma unroll
            for (int mi = 0; mi < 2; ++mi) {
                mr[mi][0] = fmaxf(mr[mi][0], __shfl_xor_sync(0xffffffffu, mr[mi][0], off));
                mr[mi][1] = fmaxf(mr[mi][1], __shfl_xor_sync(0xffffffffu, mr[mi][1], off));
            }
        if (t4 == 0) {
            float* rd = sm_red + (wid & 3) * 64;
            rd[wm + g]      = mr[0][0];
            rd[wm + g + 8]  = mr[0][1];
            rd[wm + g + 16] = mr[1][0];
            rd[wm + g + 24] = mr[1][1];
        }
        __syncthreads();
        if (tid < 64) {
            float mo = sm_m[tid];
            float mn = fmaxf(fmaxf(sm_red[tid], sm_red[64 + tid]),
                             fmaxf(sm_red[128 + tid], sm_red[192 + tid]));
            mn = fmaxf(mo, mn);
            sm_scale[tid] = expf(mo - mn);
            sm_m[tid] = mn;
        }
        __syncthreads();

        float sr[2][2] = {{0.f, 0.f}, {0.f, 0.f}};
#pragma unroll
        for (int mi = 0; mi < 2; ++mi) {
            const int rlo = wm + mi * 16 + g, rhi = rlo + 8;
            const float mlo = sm_m[rlo], mhi = sm_m[rhi];
#pragma unroll
            for (int ni = 0; ni < 4; ++ni) {
                float p0 = expf(acc_s[mi][ni][0] - mlo);
                float p1 = expf(acc_s[mi][ni][1] - mlo);
                float p2 = expf(acc_s[mi][ni][2] - mhi);
                float p3 = expf(acc_s[mi][ni][3] - mhi);
                sr[mi][0] += p0 + p1;
                sr[mi][1] += p2 + p3;
                const int col = wn + ni * 8 + 2 * t4;
                *(__half2*)(smf + FP_OFF + rlo * FP_LD + col) = __floats2half2_rn(p0, p1);
                *(__half2*)(smf + FP_OFF + rhi * FP_LD + col) = __floats2half2_rn(p2, p3);
            }
        }
#pragma unroll
        for (int off = 1; off <= 2; off <<= 1)
#pragma unroll
            for (int mi = 0; mi < 2; ++mi) {
                sr[mi][0] += __shfl_xor_sync(0xffffffffu, sr[mi][0], off);
                sr[mi][1] += __shfl_xor_sync(0xffffffffu, sr[mi][1], off);
            }
        if (t4 == 0) {
            float* rd = sm_red + (wid & 3) * 64;
            rd[wm + g]      = sr[0][0];
            rd[wm + g + 8]  = sr[0][1];
            rd[wm + g + 16] = sr[1][0];
            rd[wm + g + 24] = sr[1][1];
        }
        // rescale O by exp(m_old - m_new)
#pragma unroll
        for (int mi = 0; mi < 2; ++mi) {
            const int rlo = wm + mi * 16 + g;
            const float slo = sm_scale[rlo], shi = sm_scale[rlo + 8];
#pragma unroll
            for (int ni = 0; ni < 16; ++ni) {
                acc_o[mi][ni][0] *= slo; acc_o[mi][ni][1] *= slo;
                acc_o[mi][ni][2] *= shi; acc_o[mi][ni][3] *= shi;
            }
        }
        __syncthreads();
        if (tid < 64)
            sm_l[tid] = sm_l[tid] * sm_scale[tid] +
                        (sm_red[tid] + sm_red[64 + tid] + sm_red[128 + tid] + sm_red[192 + tid]);

        // ---------- Phase C: O += P @ V ----------
        const __half* Vg = g_VTh + (size_t)hb * DD * CC + kb * 128;
        uint4 vreg[8];
#pragma unroll
        for (int i = 0; i < 8; ++i) {
            int s = tid + i * 256;
            vreg[i] = *(const uint4*)(Vg + (size_t)(s >> 2) * CC + (s & 3) * 8);
        }
        for (int cc = 0; cc < 4; ++cc) {
            __half* Vb = smf + FV_OFF + (cc & 1) * FV_BUF;
#pragma unroll
            for (int i = 0; i < 8; ++i) {
                int s = tid + i * 256;
                *(uint4*)(Vb + (s >> 2) * FV_LD + (s & 3) * 8) = vreg[i];
            }
            __syncthreads();
            if (cc < 3) {
#pragma unroll
                for (int i = 0; i < 8; ++i) {
                    int s = tid + i * 256;
                    vreg[i] = *(const uint4*)(Vg + (size_t)(s >> 2) * CC +
                                              (cc + 1) * 32 + (s & 3) * 8);
                }
            }
#pragma unroll
            for (int k0 = 0; k0 < 32; k0 += 16) {
                uint32_t a[2][4], bf[16][2];
#pragma unroll
                for (int mi = 0; mi < 2; ++mi) {
                    const __half* ap = smf + FP_OFF + (wm + mi * 16 + g) * FP_LD +
                                       cc * 32 + k0 + 2 * t4;
                    a[mi][0] = *(const uint32_t*)ap;
                    a[mi][1] = *(const uint32_t*)(ap + 8 * FP_LD);
                    a[mi][2] = *(const uint32_t*)(ap + 8);
                    a[mi][3] = *(const uint32_t*)(ap + 8 * FP_LD + 8);
                }
#pragma unroll
                for (int ni = 0; ni < 16; ++ni) {
                    const __half* bp = Vb + (wnd + ni * 8 + g) * FV_LD + k0 + 2 * t4;
                    bf[ni][0] = *(const uint32_t*)bp;
                    bf[ni][1] = *(const uint32_t*)(bp + 8);
                }
#pragma unroll
                for (int mi = 0; mi < 2; ++mi)
#pragma unroll
                    for (int ni = 0; ni < 16; ++ni)
                        mma16(acc_o[mi][ni], a[mi], bf[ni]);
            }
        }
        __syncthreads();
    }

    // ---------- finalize: O /= l, write half ----------
#pragma unroll
    for (int mi = 0; mi < 2; ++mi) {
        const int rlo = wm + mi * 16 + g, rhi = rlo + 8;
        const float ilo = 1.0f / sm_l[rlo], ihi = 1.0f / sm_l[rhi];
        __half* olo = g_Oh + (size_t)(b * CC + q0 + rlo) * HD + (size_t)h * DD + wnd;
        __half* ohi = g_Oh + (size_t)(b * CC + q0 + rhi) * HD + (size_t)h * DD + wnd;
#pragma unroll
        for (int ni = 0; ni < 16; ++ni) {
            const int col = ni * 8 + 2 * t4;
            *(__half2*)(olo + col) = __floats2half2_rn(acc_o[mi][ni][0] * ilo,
                                                       acc_o[mi][ni][1] * ilo);
            *(__half2*)(ohi + col) = __floats2half2_rn(acc_o[mi][ni][2] * ihi,
                                                       acc_o[mi][ni][3] * ihi);
        }
    }
}

// ---------------- Kernel: final projection + bias (fp32 out) ----------------
__global__ __launch_bounds__(256, 1)
void outproj_f16(const float* __restrict__ bo, float* __restrict__ out) {
    const int m0 = blockIdx.y * 128, n0 = blockIdx.x * 256;

    ACC_INIT(acc);
    gemm_bt_h(g_Oh + (size_t)m0 * HD, HD, g_WoTh + (size_t)n0 * HD, HD, HD / 32, acc);

    const int lane = threadIdx.x & 31, wid = threadIdx.x >> 5;
    const int g = lane >> 2, t4 = lane & 3;
    const int wm = (wid >> 2) * 64, wn = (wid & 3) * 64;

#pragma unroll
    for (int mi = 0; mi < 4; ++mi) {
        const int mlo = m0 + wm + mi * 16 + g;
        const int mhi = mlo + 8;
#pragma unroll
        for (int ni = 0; ni < 8; ++ni) {
            const int n = n0 + wn + ni * 8 + 2 * t4;
            float2 bb = *(const float2*)(bo + n);
            *(float2*)(out + (size_t)mlo * DD + n) =
                make_float2(acc[mi][ni][0] + bb.x, acc[mi][ni][1] + bb.y);
            *(float2*)(out + (size_t)mhi * DD + n) =
                make_float2(acc[mi][ni][2] + bb.x, acc[mi][ni][3] + bb.y);
        }
    }
}

// ---------------- launch ----------------
extern "C" void kernel_launch(void* const* d_in, const int* in_sizes, int n_in,
                              void* d_out, int out_size) {
    (void)in_sizes; (void)n_in; (void)out_size;
    const float* x  = (const float*)d_in[0];
    const float* wq = (const float*)d_in[1];
    const float* bq = (const float*)d_in[2];
    const float* wk = (const float*)d_in[3];
    const float* bk = (const float*)d_in[4];
    const float* wv = (const float*)d_in[5];
    const float* bv = (const float*)d_in[6];
    const float* wo = (const float*)d_in[7];
    const float* bo = (const float*)d_in[8];
    float* out = (float*)d_out;

    cudaFuncSetAttribute(qkv_f16,     cudaFuncAttributeMaxDynamicSharedMemorySize, (int)SMEM_H);
    cudaFuncSetAttribute(flash_f16,   cudaFuncAttributeMaxDynamicSharedMemorySize, (int)SMEM_FLASH);
    cudaFuncSetAttribute(outproj_f16, cudaFuncAttributeMaxDynamicSharedMemorySize, (int)SMEM_H);

    __half *pWqT, *pWkT, *pWvT, *pWoT;
    cudaGetSymbolAddress((void**)&pWqT, g_WqTh);
    cudaGetSymbolAddress((void**)&pWkT, g_WkTh);
    cudaGetSymbolAddress((void**)&pWvT, g_WvTh);
    cudaGetSymbolAddress((void**)&pWoT, g_WoTh);

    rope_table_kernel<<<(CC * (DD / 2) + 255) / 256, 256>>>();
    conv_x_kernel<<<(MTOT * DD) / 256, 256>>>(x);
    transpose_h_kernel<<<dim3(16, 16, 8),  dim3(32, 8)>>>(wq, pWqT, DD, DD);
    transpose_h_kernel<<<dim3(16, 16, 8),  dim3(32, 8)>>>(wk, pWkT, DD, DD);
    transpose_h_kernel<<<dim3(16, 16, 8),  dim3(32, 8)>>>(wv, pWvT, DD, DD);
    transpose_h_kernel<<<dim3(16, 128, 1), dim3(32, 8)>>>(wo, pWoT, HD, DD);

    qkv_f16<<<dim3(2, 64, 24), 256, SMEM_H>>>(bq, bk, bv);
    vtrans_kernel<<<dim3(64, 16, 32), dim3(32, 8)>>>();
    flash_f16<<<dim3(32, 32), 256, SMEM_FLASH>>>();
    outproj_f16<<<dim3(2, 64, 1), 256, SMEM_H>>>(bo, out);
}

// round 16
// speedup vs baseline: 1.1342x; 1.1342x over previous
#include <cuda_runtime.h>
#include <cuda_fp16.h>
#include <math.h>
#include <stdint.h>

#define BB   4
#define CC   2048
#define DD   512
#define NHH  8
#define MTOT (BB * CC)      // 8192
#define HD   (NHH * DD)     // 4096

// ---------------- scratch (device globals: no allocation allowed) ----------------
__device__ __half g_Xh [(size_t)MTOT * DD];
__device__ __half g_Qh [(size_t)NHH * MTOT * DD];     // [hb][c][d]
__device__ __half g_Kh [(size_t)NHH * MTOT * DD];
__device__ __half g_Vh [(size_t)NHH * MTOT * DD];     // [hb][c][d]
__device__ __half g_VTh[(size_t)NHH * BB * DD * CC];  // [hb][d][c]
__device__ __half g_Oh [(size_t)MTOT * HD];           // [b*C+c][h*D+d]
__device__ __half g_WqTh[(size_t)NHH * DD * DD];      // [h][n][k]
__device__ __half g_WkTh[(size_t)NHH * DD * DD];
__device__ __half g_WvTh[(size_t)NHH * DD * DD];
__device__ __half g_WoTh[(size_t)DD * HD];            // [n][k]
__device__ float  g_S   [(size_t)NHH * BB * CC * CC]; // scores fp32 (masked, scaled)
__device__ float  g_part[(size_t)NHH * BB * CC * 32]; // per-(row, kt, warp) partial max
__device__ float  g_rm  [(size_t)NHH * BB * CC];      // per-row max
__device__ float  g_ctab[CC * (DD / 2)];
__device__ float  g_stab[CC * (DD / 2)];

// ---------------- RoPE cos/sin table ----------------
__global__ void rope_table_kernel() {
    int idx = blockIdx.x * blockDim.x + threadIdx.x;
    if (idx >= CC * (DD / 2)) return;
    int c = idx / (DD / 2);
    int i = idx - c * (DD / 2);
    double theta = exp((-2.0 * (double)i / (double)DD) * log(10000.0));
    double ang = fmod((double)c * theta, 6.283185307179586476925287);
    float af = (float)ang;
    g_ctab[idx] = cosf(af);
    g_stab[idx] = sinf(af);
}

// ---------------- x -> half ----------------
__global__ void conv_x_kernel(const float* __restrict__ x) {
    int i = blockIdx.x * blockDim.x + threadIdx.x;
    if (i < MTOT * DD) g_Xh[i] = __float2half_rn(x[i]);
}

// ---------------- fp32 [R][C] -> half [C][R] (batched over z) ----------------
__global__ void transpose_h_kernel(const float* __restrict__ src, __half* __restrict__ dst,
                                   int R, int C) {
    __shared__ float tsm[32][33];
    src += (size_t)blockIdx.z * R * C;
    dst += (size_t)blockIdx.z * R * C;
    int r0 = blockIdx.y * 32, c0 = blockIdx.x * 32;
    int x = threadIdx.x, y = threadIdx.y;
#pragma unroll
    for (int i = 0; i < 32; i += 8)
        tsm[y + i][x] = src[(size_t)(r0 + y + i) * C + c0 + x];
    __syncthreads();
#pragma unroll
    for (int i = 0; i < 32; i += 8)
        dst[(size_t)(c0 + y + i) * R + r0 + x] = __float2half_rn(tsm[x][y + i]);
}

// ---------------- V [hb][c][d] -> VT [hb][d][c] (half) ----------------
__global__ void vtrans_kernel() {
    __shared__ __half t[32][33];
    const int hb = blockIdx.z;
    const int c0 = blockIdx.x * 32, d0 = blockIdx.y * 32;
    const __half* src = g_Vh + ((size_t)hb * CC + c0) * DD + d0;
    __half* dst = g_VTh + (size_t)hb * DD * CC;
    int x = threadIdx.x, y = threadIdx.y;
#pragma unroll
    for (int i = 0; i < 32; i += 8)
        t[y + i][x] = src[(size_t)(y + i) * DD + x];
    __syncthreads();
#pragma unroll
    for (int i = 0; i < 32; i += 8)
        dst[(size_t)(d0 + y + i) * CC + c0 + x] = t[x][y + i];
}

// ---------------- fp16 MMA ----------------
__device__ __forceinline__ void mma16(float* d, const uint32_t* a, const uint32_t* b) {
    asm volatile(
        "mma.sync.aligned.m16n8k16.row.col.f32.f16.f16.f32 "
        "{%0,%1,%2,%3}, {%4,%5,%6,%7}, {%8,%9}, {%0,%1,%2,%3};"
        : "+f"(d[0]), "+f"(d[1]), "+f"(d[2]), "+f"(d[3])
        : "r"(a[0]), "r"(a[1]), "r"(a[2]), "r"(a[3]),
          "r"(b[0]), "r"(b[1]));
}

#define AHW    40
#define ASZ_H  (2 * 128 * AHW)
#define BSZ_H  (2 * 256 * AHW)
#define SMEM_H  (size_t)((ASZ_H + BSZ_H) * 2)           // 61440
#define SMEM_PV (SMEM_H + 1024)                         // + sm_m[128] + sm_l[128]

// =====================================================================
// generic fp16 GEMM: C[128 x 256] = A[128 x K] * B[256 x K]^T
// =====================================================================
__device__ __forceinline__ void gemm_bt_h(
    const __half* __restrict__ Ag, int lda,
    const __half* __restrict__ Bg, int ldb,
    int nchunks, float (&acc)[4][8][4])
{
    extern __shared__ __half smh[];
    __half (*As)[128][AHW] = (__half(*)[128][AHW])smh;
    __half (*Bs)[256][AHW] = (__half(*)[256][AHW])(smh + ASZ_H);

    const int tid  = threadIdx.x;
    const int lane = tid & 31, wid = tid >> 5;
    const int g = lane >> 2, t4 = lane & 3;
    const int wm = (wid >> 2) * 64, wn = (wid & 3) * 64;

    uint4 av[2], bv[4];
#pragma unroll
    for (int i = 0; i < 2; ++i) {
        int s = tid + i * 256;
        av[i] = *(const uint4*)(Ag + (size_t)(s >> 2) * lda + (s & 3) * 8);
    }
#pragma unroll
    for (int i = 0; i < 4; ++i) {
        int s = tid + i * 256;
        bv[i] = *(const uint4*)(Bg + (size_t)(s >> 2) * ldb + (s & 3) * 8);
    }

    for (int kt = 0; kt < nchunks; ++kt) {
        const int buf = kt & 1;
#pragma unroll
        for (int i = 0; i < 2; ++i) {
            int s = tid + i * 256;
            *(uint4*)&As[buf][s >> 2][(s & 3) * 8] = av[i];
        }
#pragma unroll
        for (int i = 0; i < 4; ++i) {
            int s = tid + i * 256;
            *(uint4*)&Bs[buf][s >> 2][(s & 3) * 8] = bv[i];
        }
        __syncthreads();
        if (kt + 1 < nchunks) {
            const __half* Ap = Ag + (kt + 1) * 32;
            const __half* Bp = Bg + (kt + 1) * 32;
#pragma unroll
            for (int i = 0; i < 2; ++i) {
                int s = tid + i * 256;
                av[i] = *(const uint4*)(Ap + (size_t)(s >> 2) * lda + (s & 3) * 8);
            }
#pragma unroll
            for (int i = 0; i < 4; ++i) {
                int s = tid + i * 256;
                bv[i] = *(const uint4*)(Bp + (size_t)(s >> 2) * ldb + (s & 3) * 8);
            }
        }
#pragma unroll
        for (int k0 = 0; k0 < 32; k0 += 16) {
            uint32_t a[4][4], b[8][2];
#pragma unroll
            for (int mi = 0; mi < 4; ++mi) {
                const int r = wm + mi * 16 + g;
                a[mi][0] = *(const uint32_t*)&As[buf][r][k0 + 2 * t4];
                a[mi][1] = *(const uint32_t*)&As[buf][r + 8][k0 + 2 * t4];
                a[mi][2] = *(const uint32_t*)&As[buf][r][k0 + 2 * t4 + 8];
                a[mi][3] = *(const uint32_t*)&As[buf][r + 8][k0 + 2 * t4 + 8];
            }
#pragma unroll
            for (int ni = 0; ni < 8; ++ni) {
                const int cn = wn + ni * 8 + g;
                b[ni][0] = *(const uint32_t*)&Bs[buf][cn][k0 + 2 * t4];
                b[ni][1] = *(const uint32_t*)&Bs[buf][cn][k0 + 2 * t4 + 8];
            }
#pragma unroll
            for (int mi = 0; mi < 4; ++mi)
#pragma unroll
                for (int ni = 0; ni < 8; ++ni)
                    mma16(acc[mi][ni], a[mi], b[ni]);
        }
    }
}

#define ACC_INIT(acc)                                   \
    float acc[4][8][4];                                 \
    _Pragma("unroll")                                   \
    for (int _i = 0; _i < 4; ++_i)                      \
        _Pragma("unroll")                               \
        for (int _j = 0; _j < 8; ++_j)                  \
            _Pragma("unroll")                           \
            for (int _r = 0; _r < 4; ++_r) acc[_i][_j][_r] = 0.f;

// ---------------- Kernel 1: QKV projection + bias + RoPE ----------------
__global__ __launch_bounds__(256, 1)
void qkv_f16(const float* __restrict__ bq, const float* __restrict__ bk,
             const float* __restrict__ bvv) {
    const int z = blockIdx.z;
    const int h = z / 3, t = z - 3 * h;
    const __half* WT = (t == 0 ? g_WqTh : (t == 1 ? g_WkTh : g_WvTh)) + (size_t)h * DD * DD;
    const float* bias = (t == 0 ? bq : (t == 1 ? bk : bvv)) + h * DD;
    __half* Out = (t == 0 ? g_Qh : (t == 1 ? g_Kh : g_Vh)) + (size_t)h * MTOT * DD;

    const int m0 = blockIdx.y * 128, n0 = blockIdx.x * 256;
    ACC_INIT(acc);
    gemm_bt_h(g_Xh + (size_t)m0 * DD, DD, WT + (size_t)n0 * DD, DD, DD / 32, acc);

    const int lane = threadIdx.x & 31, wid = threadIdx.x >> 5;
    const int g = lane >> 2, t4 = lane & 3;
    const int wm = (wid >> 2) * 64, wn = (wid & 3) * 64;

#pragma unroll
    for (int mi = 0; mi < 4; ++mi) {
        const int mlo = m0 + wm + mi * 16 + g;
        const int mhi = mlo + 8;
#pragma unroll
        for (int ni = 0; ni < 8; ++ni) {
            const int n = n0 + wn + ni * 8 + 2 * t4;
            float2 bb = *(const float2*)(bias + n);
            float o0 = acc[mi][ni][0] + bb.x;
            float o1 = acc[mi][ni][1] + bb.y;
            float o2 = acc[mi][ni][2] + bb.x;
            float o3 = acc[mi][ni][3] + bb.y;
            if (t < 2) {
                const int p = n >> 1;
                const int clo = mlo & (CC - 1), chi = mhi & (CC - 1);
                float cs = g_ctab[clo * 256 + p], sn = g_stab[clo * 256 + p];
                float e = o0, od = o1;
                o0 = e * cs - od * sn; o1 = e * sn + od * cs;
                cs = g_ctab[chi * 256 + p]; sn = g_stab[chi * 256 + p];
                e = o2; od = o3;
                o2 = e * cs - od * sn; o3 = e * sn + od * cs;
            }
            *(__half2*)(Out + (size_t)mlo * DD + n) = __floats2half2_rn(o0, o1);
            *(__half2*)(Out + (size_t)mhi * DD + n) = __floats2half2_rn(o2, o3);
        }
    }
}

// ---------------- Kernel 2: S = Q K^T * scale (+ per-slice row max) ----------------
// grid (8 kt, 16 qt, 32 hb); keep iff 2*kt <= qt
__global__ __launch_bounds__(256, 1)
void scores_f16() {
    const int hb = blockIdx.z, qt = blockIdx.y, kt = blockIdx.x;
    if (2 * kt > qt) return;

    const __half* Qp = g_Qh + (size_t)hb * CC * DD;
    const __half* Kp = g_Kh + (size_t)hb * CC * DD;
    float* Sp = g_S + (size_t)hb * CC * CC;
    const int m0 = qt * 128, n0 = kt * 256;

    ACC_INIT(acc);
    gemm_bt_h(Qp + (size_t)m0 * DD, DD, Kp + (size_t)n0 * DD, DD, DD / 32, acc);

    const int lane = threadIdx.x & 31, wid = threadIdx.x >> 5;
    const int g = lane >> 2, t4 = lane & 3;
    const int wm = (wid >> 2) * 64, wn = (wid & 3) * 64;
    const int wnw = wid & 3;
    const float scale = 0.04419417382415922f;  // 1/sqrt(512)

#pragma unroll
    for (int mi = 0; mi < 4; ++mi) {
        const int qlo = m0 + wm + mi * 16 + g;
        const int qhi = qlo + 8;
        float mxlo = -1e30f, mxhi = -1e30f;
#pragma unroll
        for (int ni = 0; ni < 8; ++ni) {
            const int n = n0 + wn + ni * 8 + 2 * t4;
            float o0 = (n     <= qlo) ? acc[mi][ni][0] * scale : -1e30f;
            float o1 = (n + 1 <= qlo) ? acc[mi][ni][1] * scale : -1e30f;
            float o2 = (n     <= qhi) ? acc[mi][ni][2] * scale : -1e30f;
            float o3 = (n + 1 <= qhi) ? acc[mi][ni][3] * scale : -1e30f;
            mxlo = fmaxf(mxlo, fmaxf(o0, o1));
            mxhi = fmaxf(mxhi, fmaxf(o2, o3));
            *(float2*)(Sp + (size_t)qlo * CC + n) = make_float2(o0, o1);
            *(float2*)(Sp + (size_t)qhi * CC + n) = make_float2(o2, o3);
        }
        // reduce over the 4 lanes (t4) that share each row
        mxlo = fmaxf(mxlo, __shfl_xor_sync(0xffffffffu, mxlo, 1));
        mxlo = fmaxf(mxlo, __shfl_xor_sync(0xffffffffu, mxlo, 2));
        mxhi = fmaxf(mxhi, __shfl_xor_sync(0xffffffffu, mxhi, 1));
        mxhi = fmaxf(mxhi, __shfl_xor_sync(0xffffffffu, mxhi, 2));
        if (t4 == 0) {
            g_part[(((size_t)hb * CC + qlo) * 8 + kt) * 4 + wnw] = mxlo;
            g_part[(((size_t)hb * CC + qhi) * 8 + kt) * 4 + wnw] = mxhi;
        }
    }
}

// ---------------- Kernel 3: combine partial maxima -> per-row max ----------------
// grid (256, 32), 256 threads: one warp per row
__global__ __launch_bounds__(256)
void combine_kernel() {
    const int lane = threadIdx.x & 31, w = threadIdx.x >> 5;
    const int row = blockIdx.x * 8 + w;
    const int hb = blockIdx.y;
    const int kcnt = ((row >> 8) + 1) * 4;     // valid partials (<= 32)
    const float* p = g_part + ((size_t)hb * CC + row) * 32;
    float m = (lane < kcnt) ? p[lane] : -1e30f;
#pragma unroll
    for (int off = 16; off > 0; off >>= 1)
        m = fmaxf(m, __shfl_xor_sync(0xffffffffu, m, off));
    if (lane == 0) g_rm[(size_t)hb * CC + row] = m;
}

// ---------------- Kernel 4: O = softmax(S) @ V, fused exp in staging ----------------
// grid (2 nt, 16 qt, 32 hb)
__global__ __launch_bounds__(256, 1)
void pv_f16() {
    extern __shared__ __half smh[];
    __half (*As)[128][AHW] = (__half(*)[128][AHW])smh;
    __half (*Bs)[256][AHW] = (__half(*)[256][AHW])(smh + ASZ_H);
    float* sm_m = (float*)(smh + ASZ_H + BSZ_H);   // [128]
    float* sm_l = sm_m + 128;                      // [128]

    const int hb = blockIdx.z, qt = blockIdx.y, nt = blockIdx.x;
    const float*  Sg = g_S   + (size_t)hb * CC * CC + (size_t)qt * 128 * CC;
    const __half* Vg = g_VTh + (size_t)hb * DD * CC + (size_t)nt * 256 * CC;
    const int nchunks = ((qt >> 1) + 1) * 8;       // k-extent in 32-col chunks

    const int tid = threadIdx.x, lane = tid & 31, wid = tid >> 5;
    const int g = lane >> 2, t4 = lane & 3;
    const int wm = (wid >> 2) * 64, wn = (wid & 3) * 64;

    if (tid < 128) sm_m[tid] = g_rm[(size_t)hb * CC + qt * 128 + tid];
    __syncthreads();

    const int r0 = tid >> 2, c8 = (tid & 3) * 8;   // thread's fixed A rows: r0, r0+64
    const float mr0 = sm_m[r0], mr1 = sm_m[r0 + 64];
    float lsum0 = 0.f, lsum1 = 0.f;

    ACC_INIT(acc);

    float4 af[2][2];
    uint4  bv[4];
    af[0][0] = *(const float4*)(Sg + (size_t)r0 * CC + c8);
    af[0][1] = *(const float4*)(Sg + (size_t)r0 * CC + c8 + 4);
    af[1][0] = *(const float4*)(Sg + (size_t)(r0 + 64) * CC + c8);
    af[1][1] = *(const float4*)(Sg + (size_t)(r0 + 64) * CC + c8 + 4);
#pragma unroll
    for (int i = 0; i < 4; ++i) {
        int s = tid + i * 256;
        bv[i] = *(const uint4*)(Vg + (size_t)(s >> 2) * CC + (s & 3) * 8);
    }

    for (int kt = 0; kt < nchunks; ++kt) {
        const int buf = kt & 1;
#pragma unroll
        for (int i = 0; i < 2; ++i) {
            const float mr = (i == 0) ? mr0 : mr1;
            float p0 = expf(af[i][0].x - mr), p1 = expf(af[i][0].y - mr);
            float p2 = expf(af[i][0].z - mr), p3 = expf(af[i][0].w - mr);
            float p4 = expf(af[i][1].x - mr), p5 = expf(af[i][1].y - mr);
            float p6 = expf(af[i][1].z - mr), p7 = expf(af[i][1].w - mr);
            float psum = ((p0 + p1) + (p2 + p3)) + ((p4 + p5) + (p6 + p7));
            if (i == 0) lsum0 += psum; else lsum1 += psum;
            __half2 h[4];
            h[0] = __floats2half2_rn(p0, p1); h[1] = __floats2half2_rn(p2, p3);
            h[2] = __floats2half2_rn(p4, p5); h[3] = __floats2half2_rn(p6, p7);
            *(uint4*)&As[buf][r0 + i * 64][c8] = *(uint4*)h;
        }
#pragma unroll
        for (int i = 0; i < 4; ++i) {
            int s = tid + i * 256;
            *(uint4*)&Bs[buf][s >> 2][(s & 3) * 8] = bv[i];
        }
        __syncthreads();
        if (kt + 1 < nchunks) {
            const float*  Sp = Sg + (kt + 1) * 32;
            const __half* Vp = Vg + (kt + 1) * 32;
            af[0][0] = *(const float4*)(Sp + (size_t)r0 * CC + c8);
            af[0][1] = *(const float4*)(Sp + (size_t)r0 * CC + c8 + 4);
            af[1][0] = *(const float4*)(Sp + (size_t)(r0 + 64) * CC + c8);
            af[1][1] = *(const float4*)(Sp + (size_t)(r0 + 64) * CC + c8 + 4);
#pragma unroll
            for (int i = 0; i < 4; ++i) {
                int s = tid + i * 256;
                bv[i] = *(const uint4*)(Vp + (size_t)(s >> 2) * CC + (s & 3) * 8);
            }
        }
#pragma unroll
        for (int k0 = 0; k0 < 32; k0 += 16) {
            uint32_t a[4][4], b[8][2];
#pragma unroll
            for (int mi = 0; mi < 4; ++mi) {
                const int r = wm + mi * 16 + g;
                a[mi][0] = *(const uint32_t*)&As[buf][r][k0 + 2 * t4];
                a[mi][1] = *(const uint32_t*)&As[buf][r + 8][k0 + 2 * t4];
                a[mi][2] = *(const uint32_t*)&As[buf][r][k0 + 2 * t4 + 8];
                a[mi][3] = *(const uint32_t*)&As[buf][r + 8][k0 + 2 * t4 + 8];
            }
#pragma unroll
            for (int ni = 0; ni < 8; ++ni) {
                const int cn = wn + ni * 8 + g;
                b[ni][0] = *(const uint32_t*)&Bs[buf][cn][k0 + 2 * t4];
                b[ni][1] = *(const uint32_t*)&Bs[buf][cn][k0 + 2 * t4 + 8];
            }
#pragma unroll
            for (int mi = 0; mi < 4; ++mi)
#pragma unroll
                for (int ni = 0; ni < 8; ++ni)
                    mma16(acc[mi][ni], a[mi], b[ni]);
        }
    }

    // row sums: reduce over the 4 staging threads per row (lanes tid&3)
    lsum0 += __shfl_xor_sync(0xffffffffu, lsum0, 1);
    lsum0 += __shfl_xor_sync(0xffffffffu, lsum0, 2);
    lsum1 += __shfl_xor_sync(0xffffffffu, lsum1, 1);
    lsum1 += __shfl_xor_sync(0xffffffffu, lsum1, 2);
    __syncthreads();
    if ((tid & 3) == 0) { sm_l[r0] = lsum0; sm_l[r0 + 64] = lsum1; }
    __syncthreads();

    const int h = hb >> 2, b = hb & 3;
    const int m0 = qt * 128, n0 = nt * 256;
#pragma unroll
    for (int mi = 0; mi < 4; ++mi) {
        const int rlo = wm + mi * 16 + g, rhi = rlo + 8;
        const float ilo = 1.0f / sm_l[rlo], ihi = 1.0f / sm_l[rhi];
        const int mlo = m0 + rlo, mhi = m0 + rhi;
#pragma unroll
        for (int ni = 0; ni < 8; ++ni) {
            const int n = n0 + wn + ni * 8 + 2 * t4;
            __half* plo = g_Oh + (size_t)(b * CC + mlo) * HD + (size_t)h * DD + n;
            __half* phi = g_Oh + (size_t)(b * CC + mhi) * HD + (size_t)h * DD + n;
            *(__half2*)plo = __floats2half2_rn(acc[mi][ni][0] * ilo, acc[mi][ni][1] * ilo);
            *(__half2*)phi = __floats2half2_rn(acc[mi][ni][2] * ihi, acc[mi][ni][3] * ihi);
        }
    }
}

// ---------------- Kernel 5: final projection + bias (fp32 out) ----------------
__global__ __launch_bounds__(256, 1)
void outproj_f16(const float* __restrict__ bo, float* __restrict__ out) {
    const int m0 = blockIdx.y * 128, n0 = blockIdx.x * 256;

    ACC_INIT(acc);
    gemm_bt_h(g_Oh + (size_t)m0 * HD, HD, g_WoTh + (size_t)n0 * HD, HD, HD / 32, acc);

    const int lane = threadIdx.x & 31, wid = threadIdx.x >> 5;
    const int g = lane >> 2, t4 = lane & 3;
    const int wm = (wid >> 2) * 64, wn = (wid & 3) * 64;

#pragma unroll
    for (int mi = 0; mi < 4; ++mi) {
        const int mlo = m0 + wm + mi * 16 + g;
        const int mhi = mlo + 8;
#pragma unroll
        for (int ni = 0; ni < 8; ++ni) {
            const int n = n0 + wn + ni * 8 + 2 * t4;
            float2 bb = *(const float2*)(bo + n);
            *(float2*)(out + (size_t)mlo * DD + n) =
                make_float2(acc[mi][ni][0] + bb.x, acc[mi][ni][1] + bb.y);
            *(float2*)(out + (size_t)mhi * DD + n) =
                make_float2(acc[mi][ni][2] + bb.x, acc[mi][ni][3] + bb.y);
        }
    }
}

// ---------------- launch ----------------
extern "C" void kernel_launch(void* const* d_in, const int* in_sizes, int n_in,
                              void* d_out, int out_size) {
    (void)in_sizes; (void)n_in; (void)out_size;
    const float* x  = (const float*)d_in[0];
    const float* wq = (const float*)d_in[1];
    const float* bq = (const float*)d_in[2];
    const float* wk = (const float*)d_in[3];
    const float* bk = (const float*)d_in[4];
    const float* wv = (const float*)d_in[5];
    const float* bv = (const float*)d_in[6];
    const float* wo = (const float*)d_in[7];
    const float* bo = (const float*)d_in[8];
    float* out = (float*)d_out;

    cudaFuncSetAttribute(qkv_f16,     cudaFuncAttributeMaxDynamicSharedMemorySize, (int)SMEM_H);
    cudaFuncSetAttribute(scores_f16,  cudaFuncAttributeMaxDynamicSharedMemorySize, (int)SMEM_H);
    cudaFuncSetAttribute(pv_f16,      cudaFuncAttributeMaxDynamicSharedMemorySize, (int)SMEM_PV);
    cudaFuncSetAttribute(outproj_f16, cudaFuncAttributeMaxDynamicSharedMemorySize, (int)SMEM_H);

    __half *pWqT, *pWkT, *pWvT, *pWoT;
    cudaGetSymbolAddress((void**)&pWqT, g_WqTh);
    cudaGetSymbolAddress((void**)&pWkT, g_WkTh);
    cudaGetSymbolAddress((void**)&pWvT, g_WvTh);
    cudaGetSymbolAddress((void**)&pWoT, g_WoTh);

    rope_table_kernel<<<(CC * (DD / 2) + 255) / 256, 256>>>();
    conv_x_kernel<<<(MTOT * DD) / 256, 256>>>(x);
    transpose_h_kernel<<<dim3(16, 16, 8),  dim3(32, 8)>>>(wq, pWqT, DD, DD);
    transpose_h_kernel<<<dim3(16, 16, 8),  dim3(32, 8)>>>(wk, pWkT, DD, DD);
    transpose_h_kernel<<<dim3(16, 16, 8),  dim3(32, 8)>>>(wv, pWvT, DD, DD);
    transpose_h_kernel<<<dim3(16, 128, 1), dim3(32, 8)>>>(wo, pWoT, HD, DD);

    qkv_f16<<<dim3(2, 64, 24), 256, SMEM_H>>>(bq, bk, bv);
    vtrans_kernel<<<dim3(64, 16, 32), dim3(32, 8)>>>();
    scores_f16<<<dim3(8, 16, 32), 256, SMEM_H>>>();
    combine_kernel<<<dim3(256, 32), 256>>>();
    pv_f16<<<dim3(2, 16, 32), 256, SMEM_PV>>>();
    outproj_f16<<<dim3(2, 64, 1), 256, SMEM_H>>>(bo, out);
}